// round 4
// baseline (speedup 1.0000x reference)
#include <cuda_runtime.h>
#include <cstdint>

// RealNVP: 15 coupling layers, two MLPs 1->32->16->1 per layer (leaky_relu 0.01),
// log_scale = tanh(mlp_s(x1))@sw + sb ; z2' = exp(log_scale)*x2 + mlp_t(x1)
// Output: [ concat(z1,z2) (N,2) row-major | ld (N,1) ] -> 3N floats.
//
// R4: (a) leaky_relu as max(h, 0.01h): exact, and moves 1 op/lrelu off the fma
// pipe onto the alu pipe (FMNMX is alu-pipe on sm_103a); (b) 448 threads/block
// (14 warps/SM, regs<=146) for better latency hiding. R3: fma=60.9%, issue=53.9%.

#define NLAYERS 15
#define LAYER_STRIDE 1222               // packed 8B units per layer
#define SMEM_UNITS (NLAYERS * LAYER_STRIDE)
#define SMEM_BYTES (SMEM_UNITS * 8)     // 146,640 B
#define TPB 448

__device__ __forceinline__ uint64_t pk2(float a, float b) {
    uint64_t r; asm("mov.b64 %0, {%1, %2};" : "=l"(r) : "f"(a), "f"(b)); return r;
}
__device__ __forceinline__ void up2(uint64_t v, float& a, float& b) {
    asm("mov.b64 {%0, %1}, %2;" : "=f"(a), "=f"(b) : "l"(v));
}
__device__ __forceinline__ uint64_t fma2(uint64_t a, uint64_t b, uint64_t c) {
    uint64_t d; asm("fma.rn.f32x2 %0, %1, %2, %3;" : "=l"(d) : "l"(a), "l"(b), "l"(c)); return d;
}
__device__ __forceinline__ uint64_t mul2(uint64_t a, uint64_t b) {
    uint64_t d; asm("mul.rn.f32x2 %0, %1, %2;" : "=l"(d) : "l"(a), "l"(b)); return d;
}
__device__ __forceinline__ uint64_t add2(uint64_t a, uint64_t b) {
    uint64_t d; asm("add.rn.f32x2 %0, %1, %2;" : "=l"(d) : "l"(a), "l"(b)); return d;
}

// leaky_relu(h, 0.01) == max(h, 0.01*h)  — exact; FMNMX goes to the alu pipe.
__device__ __forceinline__ uint64_t lrelu2(uint64_t h) {
    uint64_t m = mul2(h, pk2(0.01f, 0.01f));
    float a, b, c, d;
    up2(h, a, b); up2(m, c, d);
    return pk2(fmaxf(a, c), fmaxf(b, d));
}

// Per-layer per-MLP SMEM layout (packed 8B units, 16B-aligned sub-arrays):
//   [0,64)    interleaved (W1[i], b1[i]) pairs       (32 x 16B)
//   [64,576)  W2 rows: i-major, 16 packed per row    (32 x 8 x 16B)
//   [576,592) b2
//   [592,608) W3
//   [608]     b3, [609] pad
// MLP t at +610; sw at [1220], sb at [1221].

// Dual-pack MLP: two independent f32x2 inputs share every weight load.
__device__ __forceinline__ void mlp2_dual(
    uint64_t xa, uint64_t xb, const unsigned long long* __restrict__ p,
    uint64_t& oa, uint64_t& ob)
{
    uint64_t ha[16], hb[16];
    const ulonglong2* b2v = reinterpret_cast<const ulonglong2*>(p + 576);
#pragma unroll
    for (int jj = 0; jj < 8; jj++) {
        ulonglong2 b = b2v[jj];
        ha[2 * jj] = b.x; ha[2 * jj + 1] = b.y;
        hb[2 * jj] = b.x; hb[2 * jj + 1] = b.y;
    }
    const ulonglong2* w1b1 = reinterpret_cast<const ulonglong2*>(p);
    const ulonglong2* W2   = reinterpret_cast<const ulonglong2*>(p + 64);
#pragma unroll 4
    for (int i = 0; i < 32; i++) {
        ulonglong2 wb = w1b1[i];
        uint64_t h1a = lrelu2(fma2(xa, wb.x, wb.y));
        uint64_t h1b = lrelu2(fma2(xb, wb.x, wb.y));
        const ulonglong2* row = W2 + i * 8;
#pragma unroll
        for (int jj = 0; jj < 8; jj++) {
            ulonglong2 w = row[jj];
            ha[2 * jj]     = fma2(h1a, w.x, ha[2 * jj]);
            hb[2 * jj]     = fma2(h1b, w.x, hb[2 * jj]);
            ha[2 * jj + 1] = fma2(h1a, w.y, ha[2 * jj + 1]);
            hb[2 * jj + 1] = fma2(h1b, w.y, hb[2 * jj + 1]);
        }
    }
    const ulonglong2* w3v = reinterpret_cast<const ulonglong2*>(p + 592);
    uint64_t outa = p[608];
    uint64_t outb = p[608];
#pragma unroll
    for (int jj = 0; jj < 8; jj++) {
        ulonglong2 w = w3v[jj];
        outa = fma2(lrelu2(ha[2 * jj]),     w.x, outa);
        outb = fma2(lrelu2(hb[2 * jj]),     w.x, outb);
        outa = fma2(lrelu2(ha[2 * jj + 1]), w.y, outa);
        outb = fma2(lrelu2(hb[2 * jj + 1]), w.y, outb);
    }
    oa = outa; ob = outb;
}

extern __shared__ unsigned long long smw[];

__global__ __launch_bounds__(TPB, 1) void realnvp_kernel(
    const float* __restrict__ x,
    const float* __restrict__ scale_w, const float* __restrict__ scale_b,
    const float* __restrict__ sW1, const float* __restrict__ sb1,
    const float* __restrict__ sW2, const float* __restrict__ sb2,
    const float* __restrict__ sW3, const float* __restrict__ sb3,
    const float* __restrict__ tW1, const float* __restrict__ tb1,
    const float* __restrict__ tW2, const float* __restrict__ tb2,
    const float* __restrict__ tW3, const float* __restrict__ tb3,
    float* __restrict__ out, int nquads)
{
    // Stage duplicated weights into shared memory.
    for (int idx = threadIdx.x; idx < SMEM_UNITS; idx += blockDim.x) {
        int l = idx / LAYER_STRIDE;
        int k = idx - l * LAYER_STRIDE;
        float v = 0.0f;
        if (k >= 1220) {
            v = (k == 1220) ? scale_w[l] : scale_b[l];
        } else {
            const float *W1 = sW1, *b1 = sb1, *W2 = sW2, *b2 = sb2, *W3 = sW3, *b3 = sb3;
            int kk = k;
            if (k >= 610) { kk = k - 610; W1 = tW1; b1 = tb1; W2 = tW2; b2 = tb2; W3 = tW3; b3 = tb3; }
            if (kk < 64)        v = (kk & 1) ? b1[l * 32 + (kk >> 1)] : W1[l * 32 + (kk >> 1)];
            else if (kk < 576)  v = W2[l * 512 + (kk - 64)];
            else if (kk < 592)  v = b2[l * 16 + (kk - 576)];
            else if (kk < 608)  v = W3[l * 16 + (kk - 592)];
            else if (kk == 608) v = b3[l];
            else                v = 0.0f;   // pad
        }
        smw[idx] = pk2(v, v);
    }
    __syncthreads();

    const int stride = gridDim.x * blockDim.x;
    for (int q = blockIdx.x * blockDim.x + threadIdx.x; q < nquads; q += stride) {
        float4 xv0 = *reinterpret_cast<const float4*>(x + 8 * (size_t)q);
        float4 xv1 = *reinterpret_cast<const float4*>(x + 8 * (size_t)q + 4);
        // pack a = points 4q,4q+1 ; pack b = points 4q+2,4q+3
        uint64_t z1a = pk2(xv0.y, xv0.w), z2a = pk2(xv0.x, xv0.z);
        uint64_t z1b = pk2(xv1.y, xv1.w), z2b = pk2(xv1.x, xv1.z);
        uint64_t lda = 0, ldb = 0;

#pragma unroll 1
        for (int l = 0; l < NLAYERS; l++) {
            const unsigned long long* base = smw + l * LAYER_STRIDE;
            uint64_t x1a = z2a, x2a = z1a;
            uint64_t x1b = z2b, x2b = z1b;

            uint64_t sa, sb_;
            mlp2_dual(x1a, x1b, base, sa, sb_);
            float a0, a1, b0, b1;
            up2(sa, a0, a1); up2(sb_, b0, b1);
            uint64_t tha = pk2(tanhf(a0), tanhf(a1));
            uint64_t thb = pk2(tanhf(b0), tanhf(b1));
            uint64_t logsa = fma2(tha, base[1220], base[1221]);
            uint64_t logsb = fma2(thb, base[1220], base[1221]);

            uint64_t ta, tb;
            mlp2_dual(x1a, x1b, base + 610, ta, tb);

            up2(logsa, a0, a1); up2(logsb, b0, b1);
            uint64_t exa = pk2(__expf(a0), __expf(a1));
            uint64_t exb = pk2(__expf(b0), __expf(b1));
            uint64_t z2na = fma2(exa, x2a, ta);
            uint64_t z2nb = fma2(exb, x2b, tb);

            lda = add2(lda, logsa);
            ldb = add2(ldb, logsb);
            z1a = x1a; z2a = z2na;
            z1b = x1b; z2b = z2nb;
        }

        float z1a0, z1a1, z2a0, z2a1, z1b0, z1b1, z2b0, z2b1;
        float la0, la1, lb0, lb1;
        up2(z1a, z1a0, z1a1); up2(z2a, z2a0, z2a1);
        up2(z1b, z1b0, z1b1); up2(z2b, z2b0, z2b1);
        up2(lda, la0, la1);   up2(ldb, lb0, lb1);

        float4 o0; o0.x = z1a0; o0.y = z2a0; o0.z = z1a1; o0.w = z2a1;
        float4 o1; o1.x = z1b0; o1.y = z2b0; o1.z = z1b1; o1.w = z2b1;
        *reinterpret_cast<float4*>(out + 8 * (size_t)q)     = o0;
        *reinterpret_cast<float4*>(out + 8 * (size_t)q + 4) = o1;
        float4 lo; lo.x = la0; lo.y = la1; lo.z = lb0; lo.w = lb1;
        *reinterpret_cast<float4*>(out + 8 * (size_t)nquads + 4 * (size_t)q) = lo;
    }
}

extern "C" void kernel_launch(void* const* d_in, const int* in_sizes, int n_in,
                              void* d_out, int out_size) {
    const float* x       = (const float*)d_in[0];
    const float* scale_w = (const float*)d_in[1];
    const float* scale_b = (const float*)d_in[2];
    const float* sW1 = (const float*)d_in[3];
    const float* sb1 = (const float*)d_in[4];
    const float* sW2 = (const float*)d_in[5];
    const float* sb2 = (const float*)d_in[6];
    const float* sW3 = (const float*)d_in[7];
    const float* sb3 = (const float*)d_in[8];
    const float* tW1 = (const float*)d_in[9];
    const float* tb1 = (const float*)d_in[10];
    const float* tW2 = (const float*)d_in[11];
    const float* tb2 = (const float*)d_in[12];
    const float* tW3 = (const float*)d_in[13];
    const float* tb3 = (const float*)d_in[14];
    float* out = (float*)d_out;

    int nquads = in_sizes[0] / 8;   // x has N*2 floats; 4 points per thread

    cudaFuncSetAttribute(realnvp_kernel, cudaFuncAttributeMaxDynamicSharedMemorySize, SMEM_BYTES);
    realnvp_kernel<<<148, TPB, SMEM_BYTES>>>(
        x, scale_w, scale_b, sW1, sb1, sW2, sb2, sW3, sb3,
        tW1, tb1, tW2, tb2, tW3, tb3, out, nquads);
}

// round 5
// speedup vs baseline: 1.4000x; 1.4000x over previous
#include <cuda_runtime.h>
#include <cstdint>

// RealNVP: 15 coupling layers, two MLPs 1->32->16->1 per layer (leaky_relu 0.01),
// log_scale = tanh(mlp_s(x1))@sw + sb ; z2' = exp(log_scale)*x2 + mlp_t(x1)
// Output: [ concat(z1,z2) (N,2) row-major | ld (N,1) ] -> 3N floats.
//
// R5: hidden-unit packing. h2 accumulators hold (j, j+1) pairs per point, so W2
// and W3 weights are consumed as NATURAL consecutive pairs from smem (no
// duplication). LDS per inner-i drops 9 -> 5 (R3 was LDS/FMA parity bound:
// L1=56%, fma=61%). The scalar h1 is duplicated into (h1,h1) packs via cheap
// register MOVs on the idle alu pipe. FMA work and order unchanged. lrelu back
// to R3's LOP3 form (R4's fmaxf variant bloated the mov count and regressed).

#define NLAYERS 15
#define LAYER_STRIDE 678                // packed 8B units per layer
#define SMEM_UNITS (NLAYERS * LAYER_STRIDE)
#define SMEM_BYTES (SMEM_UNITS * 8)     // 81,360 B
#define TPB 384

__device__ __forceinline__ uint64_t pk2(float a, float b) {
    uint64_t r; asm("mov.b64 %0, {%1, %2};" : "=l"(r) : "f"(a), "f"(b)); return r;
}
__device__ __forceinline__ uint64_t dup2(float a) {
    uint64_t r; asm("mov.b64 %0, {%1, %1};" : "=l"(r) : "f"(a)); return r;
}
__device__ __forceinline__ void up2(uint64_t v, float& a, float& b) {
    asm("mov.b64 {%0, %1}, %2;" : "=f"(a), "=f"(b) : "l"(v));
}
__device__ __forceinline__ uint64_t fma2(uint64_t a, uint64_t b, uint64_t c) {
    uint64_t d; asm("fma.rn.f32x2 %0, %1, %2, %3;" : "=l"(d) : "l"(a), "l"(b), "l"(c)); return d;
}
__device__ __forceinline__ uint64_t mul2(uint64_t a, uint64_t b) {
    uint64_t d; asm("mul.rn.f32x2 %0, %1, %2;" : "=l"(d) : "l"(a), "l"(b)); return d;
}
__device__ __forceinline__ uint64_t add2(uint64_t a, uint64_t b) {
    uint64_t d; asm("add.rn.f32x2 %0, %1, %2;" : "=l"(d) : "l"(a), "l"(b)); return d;
}

// leaky_relu(h, 0.01) == 0.505*h + 0.495*|h|   (branch-free, packed; LOP3 abs)
__device__ __forceinline__ uint64_t lrelu2(uint64_t h) {
    uint64_t a = h & 0x7FFFFFFF7FFFFFFFULL;
    uint64_t m = mul2(h, pk2(0.505f, 0.505f));
    return fma2(a, pk2(0.495f, 0.495f), m);
}

// Per-layer per-MLP SMEM layout (8B units; every sub-array 16B-aligned):
//   [0,64)    interleaved DUPLICATED (W1[i],W1[i]),(b1[i],b1[i])   (32 x 16B)
//   [64,320)  W2 rows, PLAIN pairs: row i = 16 floats = 8 units    (32 x 4 x 16B)
//   [320,328) b2 plain pairs
//   [328,336) W3 plain pairs
//   [336]     (b3, 0.0f), [337] pad
// MLP t at +338; sw dup at [676], sb dup at [677]. LAYER_STRIDE=678.

// Quad MLP: 4 points (xa = pts 0,1 ; xb = pts 2,3) share every weight load.
// h2 accumulators are packed over hidden-unit pairs (j, j+1) per point.
__device__ __forceinline__ void mlp2_quad(
    uint64_t xa, uint64_t xb, const unsigned long long* __restrict__ p,
    uint64_t& oa, uint64_t& ob)
{
    uint64_t h0[8], h1r[8], h2r[8], h3r[8];
    const ulonglong2* b2v = reinterpret_cast<const ulonglong2*>(p + 320);
#pragma unroll
    for (int jj = 0; jj < 4; jj++) {
        ulonglong2 b = b2v[jj];
        h0[2*jj] = b.x;  h0[2*jj+1] = b.y;
        h1r[2*jj] = b.x; h1r[2*jj+1] = b.y;
        h2r[2*jj] = b.x; h2r[2*jj+1] = b.y;
        h3r[2*jj] = b.x; h3r[2*jj+1] = b.y;
    }
    const ulonglong2* w1b1 = reinterpret_cast<const ulonglong2*>(p);
    const ulonglong2* W2   = reinterpret_cast<const ulonglong2*>(p + 64);
#pragma unroll 4
    for (int i = 0; i < 32; i++) {
        ulonglong2 wb = w1b1[i];
        uint64_t ha = lrelu2(fma2(xa, wb.x, wb.y));   // (h1_p0, h1_p1)
        uint64_t hb = lrelu2(fma2(xb, wb.x, wb.y));   // (h1_p2, h1_p3)
        float f0, f1, f2, f3;
        up2(ha, f0, f1); up2(hb, f2, f3);
        uint64_t d0 = dup2(f0), d1 = dup2(f1), d2 = dup2(f2), d3 = dup2(f3);
        const ulonglong2* row = W2 + i * 4;           // 16 floats, natural pairs
#pragma unroll
        for (int jj = 0; jj < 4; jj++) {
            ulonglong2 w = row[jj];
            h0[2*jj]   = fma2(d0, w.x, h0[2*jj]);
            h1r[2*jj]  = fma2(d1, w.x, h1r[2*jj]);
            h2r[2*jj]  = fma2(d2, w.x, h2r[2*jj]);
            h3r[2*jj]  = fma2(d3, w.x, h3r[2*jj]);
            h0[2*jj+1] = fma2(d0, w.y, h0[2*jj+1]);
            h1r[2*jj+1]= fma2(d1, w.y, h1r[2*jj+1]);
            h2r[2*jj+1]= fma2(d2, w.y, h2r[2*jj+1]);
            h3r[2*jj+1]= fma2(d3, w.y, h3r[2*jj+1]);
        }
    }
    const ulonglong2* w3v = reinterpret_cast<const ulonglong2*>(p + 328);
    uint64_t b3p = p[336];                            // (b3, 0)
    uint64_t a0 = b3p, a1 = b3p, a2 = b3p, a3 = b3p;
#pragma unroll
    for (int jj = 0; jj < 4; jj++) {
        ulonglong2 w = w3v[jj];
        a0 = fma2(lrelu2(h0[2*jj]),  w.x, a0);  a0 = fma2(lrelu2(h0[2*jj+1]),  w.y, a0);
        a1 = fma2(lrelu2(h1r[2*jj]), w.x, a1);  a1 = fma2(lrelu2(h1r[2*jj+1]), w.y, a1);
        a2 = fma2(lrelu2(h2r[2*jj]), w.x, a2);  a2 = fma2(lrelu2(h2r[2*jj+1]), w.y, a2);
        a3 = fma2(lrelu2(h3r[2*jj]), w.x, a3);  a3 = fma2(lrelu2(h3r[2*jj+1]), w.y, a3);
    }
    float s0, s1, t0, t1, u0, u1, v0, v1;
    up2(a0, s0, s1); up2(a1, t0, t1); up2(a2, u0, u1); up2(a3, v0, v1);
    oa = pk2(s0 + s1, t0 + t1);
    ob = pk2(u0 + u1, v0 + v1);
}

extern __shared__ unsigned long long smw[];

__global__ __launch_bounds__(TPB, 1) void realnvp_kernel(
    const float* __restrict__ x,
    const float* __restrict__ scale_w, const float* __restrict__ scale_b,
    const float* __restrict__ sW1, const float* __restrict__ sb1,
    const float* __restrict__ sW2, const float* __restrict__ sb2,
    const float* __restrict__ sW3, const float* __restrict__ sb3,
    const float* __restrict__ tW1, const float* __restrict__ tb1,
    const float* __restrict__ tW2, const float* __restrict__ tb2,
    const float* __restrict__ tW3, const float* __restrict__ tb3,
    float* __restrict__ out, int nquads)
{
    // Stage weights into shared memory (W1/b1/sw/sb duplicated; rest plain pairs).
    for (int idx = threadIdx.x; idx < SMEM_UNITS; idx += blockDim.x) {
        int l = idx / LAYER_STRIDE;
        int k = idx - l * LAYER_STRIDE;
        unsigned long long unit;
        if (k == 676) { float v = scale_w[l]; unit = pk2(v, v); }
        else if (k == 677) { float v = scale_b[l]; unit = pk2(v, v); }
        else {
            const float *W1 = sW1, *b1 = sb1, *W2 = sW2, *b2 = sb2, *W3 = sW3, *b3 = sb3;
            int kk = k;
            if (k >= 338) { kk = k - 338; W1 = tW1; b1 = tb1; W2 = tW2; b2 = tb2; W3 = tW3; b3 = tb3; }
            if (kk < 64) {
                float v = (kk & 1) ? b1[l * 32 + (kk >> 1)] : W1[l * 32 + (kk >> 1)];
                unit = pk2(v, v);
            } else if (kk < 320) {
                int j = (kk - 64) * 2;
                unit = pk2(W2[l * 512 + j], W2[l * 512 + j + 1]);
            } else if (kk < 328) {
                int j = (kk - 320) * 2;
                unit = pk2(b2[l * 16 + j], b2[l * 16 + j + 1]);
            } else if (kk < 336) {
                int j = (kk - 328) * 2;
                unit = pk2(W3[l * 16 + j], W3[l * 16 + j + 1]);
            } else if (kk == 336) {
                unit = pk2(b3[l], 0.0f);
            } else {
                unit = 0ull;   // pad
            }
        }
        smw[idx] = unit;
    }
    __syncthreads();

    const int stride = gridDim.x * blockDim.x;
    for (int q = blockIdx.x * blockDim.x + threadIdx.x; q < nquads; q += stride) {
        float4 xv0 = *reinterpret_cast<const float4*>(x + 8 * (size_t)q);
        float4 xv1 = *reinterpret_cast<const float4*>(x + 8 * (size_t)q + 4);
        // pack a = points 4q,4q+1 ; pack b = points 4q+2,4q+3
        uint64_t z1a = pk2(xv0.y, xv0.w), z2a = pk2(xv0.x, xv0.z);
        uint64_t z1b = pk2(xv1.y, xv1.w), z2b = pk2(xv1.x, xv1.z);
        uint64_t lda = 0, ldb = 0;

#pragma unroll 1
        for (int l = 0; l < NLAYERS; l++) {
            const unsigned long long* base = smw + l * LAYER_STRIDE;
            uint64_t x1a = z2a, x2a = z1a;
            uint64_t x1b = z2b, x2b = z1b;

            uint64_t sa, sb_;
            mlp2_quad(x1a, x1b, base, sa, sb_);
            float a0, a1, b0, b1;
            up2(sa, a0, a1); up2(sb_, b0, b1);
            uint64_t tha = pk2(tanhf(a0), tanhf(a1));
            uint64_t thb = pk2(tanhf(b0), tanhf(b1));
            uint64_t logsa = fma2(tha, base[676], base[677]);
            uint64_t logsb = fma2(thb, base[676], base[677]);

            uint64_t ta, tb;
            mlp2_quad(x1a, x1b, base + 338, ta, tb);

            up2(logsa, a0, a1); up2(logsb, b0, b1);
            uint64_t exa = pk2(__expf(a0), __expf(a1));
            uint64_t exb = pk2(__expf(b0), __expf(b1));
            uint64_t z2na = fma2(exa, x2a, ta);
            uint64_t z2nb = fma2(exb, x2b, tb);

            lda = add2(lda, logsa);
            ldb = add2(ldb, logsb);
            z1a = x1a; z2a = z2na;
            z1b = x1b; z2b = z2nb;
        }

        float z1a0, z1a1, z2a0, z2a1, z1b0, z1b1, z2b0, z2b1;
        float la0, la1, lb0, lb1;
        up2(z1a, z1a0, z1a1); up2(z2a, z2a0, z2a1);
        up2(z1b, z1b0, z1b1); up2(z2b, z2b0, z2b1);
        up2(lda, la0, la1);   up2(ldb, lb0, lb1);

        float4 o0; o0.x = z1a0; o0.y = z2a0; o0.z = z1a1; o0.w = z2a1;
        float4 o1; o1.x = z1b0; o1.y = z2b0; o1.z = z1b1; o1.w = z2b1;
        *reinterpret_cast<float4*>(out + 8 * (size_t)q)     = o0;
        *reinterpret_cast<float4*>(out + 8 * (size_t)q + 4) = o1;
        float4 lo; lo.x = la0; lo.y = la1; lo.z = lb0; lo.w = lb1;
        *reinterpret_cast<float4*>(out + 8 * (size_t)nquads + 4 * (size_t)q) = lo;
    }
}

extern "C" void kernel_launch(void* const* d_in, const int* in_sizes, int n_in,
                              void* d_out, int out_size) {
    const float* x       = (const float*)d_in[0];
    const float* scale_w = (const float*)d_in[1];
    const float* scale_b = (const float*)d_in[2];
    const float* sW1 = (const float*)d_in[3];
    const float* sb1 = (const float*)d_in[4];
    const float* sW2 = (const float*)d_in[5];
    const float* sb2 = (const float*)d_in[6];
    const float* sW3 = (const float*)d_in[7];
    const float* sb3 = (const float*)d_in[8];
    const float* tW1 = (const float*)d_in[9];
    const float* tb1 = (const float*)d_in[10];
    const float* tW2 = (const float*)d_in[11];
    const float* tb2 = (const float*)d_in[12];
    const float* tW3 = (const float*)d_in[13];
    const float* tb3 = (const float*)d_in[14];
    float* out = (float*)d_out;

    int nquads = in_sizes[0] / 8;   // x has N*2 floats; 4 points per thread

    cudaFuncSetAttribute(realnvp_kernel, cudaFuncAttributeMaxDynamicSharedMemorySize, SMEM_BYTES);
    realnvp_kernel<<<148, TPB, SMEM_BYTES>>>(
        x, scale_w, scale_b, sW1, sb1, sW2, sb2, sW3, sb3,
        tW1, tb1, tW2, tb2, tW3, tb3, out, nquads);
}